// round 11
// baseline (speedup 1.0000x reference)
#include <cuda_runtime.h>
#include <math.h>

#define NQ 19
#define NL 3
#define NA 8
#define NSTATE (1u << NQ)   // 524288 amplitudes, 4 MiB as float2

__device__ float2 g_state[NSTATE];

__device__ __forceinline__ float2 cmul(float2 a, float2 b) {
    return make_float2(a.x * b.x - a.y * b.y, a.x * b.y + a.y * b.x);
}

// ---------------------------------------------------------------------------
// Build one layer's fused 2x2 unitaries U = (RZ)*RY*RX into smem.
// Layer NL-1 omits RZ (diagonal; cannot change probabilities).
// All threads must call (contains __syncthreads).
// ---------------------------------------------------------------------------
template<int LAYER>
__device__ __forceinline__ void build_U(float2 (*sU)[4],
                                        const float* __restrict__ inputs,
                                        const float* __restrict__ yw,
                                        const float* __restrict__ zw)
{
    int w = threadIdx.x;
    if (w < NQ) {
        const float TWO_PI = 6.28318530717958647692f;
        const float PI_F   = 3.14159265358979323846f;

        float x = inputs[w];
        float a;
        if (w >= NQ - 2) {                       // directional wires
            a = (x >= 0.5f) ? PI_F : 0.0f;
        } else {                                 // [-1.5,1.5] -> [0,2pi], clip
            a = (x + 1.5f) * (TWO_PI / 3.0f);
            a = fminf(fmaxf(a, 0.0f), TWO_PI);
        }

        float sx, cx; sincosf(0.5f * a, &sx, &cx);
        float y = yw[LAYER * NQ + w];
        float sy, cy; sincosf(0.5f * y, &sy, &cy);

        // M = RY*RX; RX = [[cx,-i sx],[-i sx,cx]], RY = [[cy,-sy],[sy,cy]]
        float2 m00 = make_float2(cy * cx, sy * sx);
        float2 m01 = make_float2(-sy * cx, -cy * sx);
        float2 m10 = make_float2(sy * cx, -cy * sx);
        float2 m11 = make_float2(cy * cx, -sy * sx);

        if (LAYER < NL - 1) {                    // fold RZ
            float z = zw[LAYER * NQ + w];
            float sz, cz; sincosf(0.5f * z, &sz, &cz);
            float2 e0 = make_float2(cz, -sz);
            float2 e1 = make_float2(cz,  sz);
            m00 = cmul(e0, m00); m01 = cmul(e0, m01);
            m10 = cmul(e1, m10); m11 = cmul(e1, m11);
        }
        sU[w][0] = m00; sU[w][1] = m01;
        sU[w][2] = m10; sU[w][3] = m11;
    }
    __syncthreads();
}

// Gate on the register pair (2 amps per thread: indices 0,1).
__device__ __forceinline__ void gate_pair(float vr[2], float vi[2], const float2* u)
{
    float2 u00 = u[0], u01 = u[1], u10 = u[2], u11 = u[3];
    float ar = vr[0], ai = vi[0], br = vr[1], bi = vi[1];
    vr[0] = u00.x * ar - u00.y * ai + u01.x * br - u01.y * bi;
    vi[0] = u00.x * ai + u00.y * ar + u01.x * bi + u01.y * br;
    vr[1] = u10.x * ar - u10.y * ai + u11.x * br - u11.y * bi;
    vi[1] = u10.x * ai + u10.y * ar + u11.x * bi + u11.y * br;
}

// Gate on a lane bit (mask M) via warp shuffles, N amps per thread.
template<int M, int N>
__device__ __forceinline__ void gate_lane(float* vr, float* vi,
                                          unsigned lane, const float2* u)
{
    bool hi = (lane & M) != 0;
    float2 A = hi ? u[3] : u[0];   // coefficient of own amp
    float2 B = hi ? u[2] : u[1];   // coefficient of partner amp
    #pragma unroll
    for (int r = 0; r < N; r++) {
        float wr = __shfl_xor_sync(0xFFFFFFFFu, vr[r], M);
        float wi = __shfl_xor_sync(0xFFFFFFFFu, vi[r], M);
        float ar = vr[r], ai = vi[r];
        vr[r] = A.x * ar - A.y * ai + B.x * wr - B.y * wi;
        vi[r] = A.x * ai + A.y * ar + B.x * wi + B.y * wr;
    }
}

__device__ __forceinline__ float cz_sign(unsigned g)
{
    unsigned par = __popc((g & (g >> 1)) & 0x3FFFFu) + ((g & (g >> 18)) & 1u);
    return (par & 1u) ? -1.0f : 1.0f;
}

// ========================= LOW PASS (wires 0..9) ===========================
// 512 threads t[8:0], 2 amps/thread, tile 1024 amps, grid 512 (blk = g[18:10]).
// Phase 1 layout: a = (r<<9)|t  (lane=a[4:0]=w0..4, warp=a[8:5], reg a9=w9).
// Phase 2 layout: a[4:0]=t[7:3], a5=r (w5), a6=t0 (w6), a7=t1 (w7),
//                 a8=t2 (w8), a9=t8.
__device__ __forceinline__ unsigned low_p2a(unsigned t, unsigned r)
{
    return ((t >> 3) & 31u) | (r << 5) | ((t & 1u) << 6)
         | (((t >> 1) & 1u) << 7) | (((t >> 2) & 1u) << 8)
         | (((t >> 8) & 1u) << 9);
}
// bank swizzle: s[4:2] ^= a[8:6] -> both phases conflict-free
__device__ __forceinline__ unsigned low_swz(unsigned a)
{
    return a ^ (((a >> 6) & 7u) << 2);
}

// Low-pass gate core: in phase-1 layout regs -> out phase-2 layout regs.
__device__ __forceinline__ void low_gates(float vr[2], float vi[2],
                                          float2 (*sU)[4],
                                          float* sre, float* sim,
                                          unsigned tid, unsigned lane)
{
    gate_pair(vr, vi, sU[9]);
    gate_lane<1, 2>(vr, vi, lane, sU[0]);
    gate_lane<2, 2>(vr, vi, lane, sU[1]);
    gate_lane<4, 2>(vr, vi, lane, sU[2]);
    gate_lane<8, 2>(vr, vi, lane, sU[3]);
    gate_lane<16,2>(vr, vi, lane, sU[4]);

    #pragma unroll
    for (int r = 0; r < 2; r++) {
        unsigned s = low_swz((unsigned)(r << 9) | tid);
        sre[s] = vr[r]; sim[s] = vi[r];
    }
    __syncthreads();
    #pragma unroll
    for (int r = 0; r < 2; r++) {
        unsigned s = low_swz(low_p2a(tid, r));
        vr[r] = sre[s]; vi[r] = sim[s];
    }

    gate_pair(vr, vi, sU[5]);
    gate_lane<1, 2>(vr, vi, lane, sU[6]);
    gate_lane<2, 2>(vr, vi, lane, sU[7]);
    gate_lane<4, 2>(vr, vi, lane, sU[8]);
}

// Kernel 1: layer-0 product state (+CZ0 sign) synthesized in registers,
// then layer-1 low gates. Write-only.
__global__ void __launch_bounds__(512) init_low_kernel(const float* __restrict__ inputs,
                                                       const float* __restrict__ yw,
                                                       const float* __restrict__ zw,
                                                       float* __restrict__ out)
{
    __shared__ float2 sU0[NQ][4];
    __shared__ float2 sU1[NQ][4];
    __shared__ float sre[1024];
    __shared__ float sim[1024];
    build_U<0>(sU0, inputs, yw, zw);
    build_U<1>(sU1, inputs, yw, zw);

    const unsigned tid  = threadIdx.x;
    const unsigned lane = tid & 31u;
    const unsigned blk  = blockIdx.x;
    const unsigned base = blk << 10;
    if (blk == 0 && tid < NA) out[tid] = 0.0f;

    // product factor: wires 0..8 from tid bits, 10..18 from blk bits
    float2 Pc = sU0[0][(tid & 1u) ? 2 : 0];
    #pragma unroll
    for (int w = 1; w < 9; w++)
        Pc = cmul(Pc, sU0[w][((tid >> w) & 1u) ? 2 : 0]);
    #pragma unroll
    for (int w = 10; w < NQ; w++)
        Pc = cmul(Pc, sU0[w][((blk >> (w - 10)) & 1u) ? 2 : 0]);

    float vr[2], vi[2];
    #pragma unroll
    for (int r = 0; r < 2; r++) {
        float2 amp = cmul(Pc, sU0[9][r ? 2 : 0]);   // wire 9 = reg bit
        unsigned g = base | (unsigned)(r << 9) | tid;
        float s = cz_sign(g);
        vr[r] = s * amp.x; vi[r] = s * amp.y;
    }

    low_gates(vr, vi, sU1, sre, sim, tid, lane);

    #pragma unroll
    for (int r = 0; r < 2; r++)
        g_state[base | low_p2a(tid, r)] = make_float2(vr[r], vi[r]);
}

// Kernel 3: layer-2 low pass (read-modify-write).
__global__ void __launch_bounds__(512) low2_kernel(const float* __restrict__ inputs,
                                                   const float* __restrict__ yw,
                                                   const float* __restrict__ zw)
{
    __shared__ float2 sU[NQ][4];
    __shared__ float sre[1024];
    __shared__ float sim[1024];
    build_U<2>(sU, inputs, yw, zw);

    const unsigned tid  = threadIdx.x;
    const unsigned lane = tid & 31u;
    const unsigned base = blockIdx.x << 10;

    float vr[2], vi[2];
    #pragma unroll
    for (int r = 0; r < 2; r++) {
        float2 a = g_state[base | (unsigned)(r << 9) | tid];
        vr[r] = a.x; vi[r] = a.y;
    }

    low_gates(vr, vi, sU, sre, sim, tid, lane);

    #pragma unroll
    for (int r = 0; r < 2; r++)
        g_state[base | low_p2a(tid, r)] = make_float2(vr[r], vi[r]);
}

// ========================= HIGH PASS (wires 10..18) ========================
// Local bits a[9:0]: a0 = g[0] pad, a[9:1] = g[18:10] (wire w at a[w-9]);
// blk = g[9:1] (9 bits, grid 512). Each thread owns one float4 (a0 = 0,1).
// Phase 1: a[9:1] = t; lane gates w10..14 (a[5:1]); warp bits a[9:6] = w15..18.
// Phase 2: a6=t0 (w15), a7=t1 (w16), a8=t2 (w17), a9=t3 (w18),
//          a[5:1]=t[8:4]; gates are 4 lane gates.
__device__ __forceinline__ unsigned high_p2idx(unsigned t)   // idx = a[9:1]
{
    return ((t >> 4) & 31u) | ((t & 1u) << 5) | (((t >> 1) & 1u) << 6)
         | (((t >> 2) & 1u) << 7) | (((t >> 3) & 1u) << 8);
}
// bank swizzle on float4 index: s[4:1] ^= idx[8:5]
__device__ __forceinline__ unsigned high_swz(unsigned idx)
{
    return idx ^ (((idx >> 5) & 15u) << 1);
}

template<int LAYER, bool LAST>
__global__ void __launch_bounds__(512) highpass_kernel(const float* __restrict__ inputs,
                                                       const float* __restrict__ yw,
                                                       const float* __restrict__ zw,
                                                       float* __restrict__ out)
{
    __shared__ float2 sU[NQ][4];
    __shared__ float4 sv[512];
    build_U<LAYER>(sU, inputs, yw, zw);

    const unsigned tid  = threadIdx.x;
    const unsigned lane = tid & 31u;
    const unsigned blk  = blockIdx.x;

    const float4* gs4 = (const float4*)g_state;
    float4 v = gs4[((unsigned)tid << 9) | blk];
    float vr[2] = { v.x, v.z };
    float vi[2] = { v.y, v.w };

    gate_lane<1, 2>(vr, vi, lane, sU[10]);
    gate_lane<2, 2>(vr, vi, lane, sU[11]);
    gate_lane<4, 2>(vr, vi, lane, sU[12]);
    gate_lane<8, 2>(vr, vi, lane, sU[13]);
    gate_lane<16,2>(vr, vi, lane, sU[14]);

    sv[high_swz(tid)] = make_float4(vr[0], vi[0], vr[1], vi[1]);
    __syncthreads();
    const unsigned idx2 = high_p2idx(tid);
    float4 w = sv[high_swz(idx2)];
    vr[0] = w.x; vi[0] = w.y; vr[1] = w.z; vi[1] = w.w;

    gate_lane<1, 2>(vr, vi, lane, sU[15]);
    gate_lane<2, 2>(vr, vi, lane, sU[16]);
    gate_lane<4, 2>(vr, vi, lane, sU[17]);
    gate_lane<8, 2>(vr, vi, lane, sU[18]);

    if (!LAST) {
        unsigned g0 = (idx2 << 10) | (blk << 1);
        float s0 = cz_sign(g0), s1 = cz_sign(g0 | 1u);
        float4* go4 = (float4*)g_state;
        go4[(idx2 << 9) | blk] = make_float4(s0 * vr[0], s0 * vi[0],
                                             s1 * vr[1], s1 * vi[1]);
    } else {
        // wire0 = a0 (the register pair); wires 1..7 = blk[6:0] (uniform)
        float p0 = vr[0] * vr[0] + vi[0] * vi[0];
        float p1 = vr[1] * vr[1] + vi[1] * vi[1];
        float P  = p0 + p1;
        float S0 = p0 - p1;
        #pragma unroll
        for (int o = 16; o > 0; o >>= 1) {
            P  += __shfl_xor_sync(0xFFFFFFFFu, P,  o);
            S0 += __shfl_xor_sync(0xFFFFFFFFu, S0, o);
        }
        __syncthreads();                  // done reading sv; reuse as scratch
        float* sf = (float*)sv;
        if (lane == 0) {
            unsigned wi = tid >> 5;       // 16 warps
            sf[wi]      = P;
            sf[16 + wi] = S0;
        }
        __syncthreads();
        if (tid == 0) {
            float Pt = 0.f, S0t = 0.f;
            #pragma unroll
            for (int i = 0; i < 16; i++) { Pt += sf[i]; S0t += sf[16 + i]; }
            atomicAdd(out + 0, S0t);
            #pragma unroll
            for (int w2 = 1; w2 < 8; w2++) {
                float sgn = ((blk >> (w2 - 1)) & 1u) ? -1.f : 1.f;
                atomicAdd(out + w2, sgn * Pt);
            }
        }
    }
}

extern "C" void kernel_launch(void* const* d_in, const int* in_sizes, int n_in,
                              void* d_out, int out_size)
{
    (void)in_sizes; (void)n_in; (void)out_size;
    const float* inputs = (const float*)d_in[0];
    const float* yw     = (const float*)d_in[1];
    const float* zw     = (const float*)d_in[2];
    float* out = (float*)d_out;

    init_low_kernel<<<512, 512>>>(inputs, yw, zw, out);            // L0 + L1 low
    highpass_kernel<1, false><<<512, 512>>>(inputs, yw, zw, out);  // L1 high + CZ
    low2_kernel<<<512, 512>>>(inputs, yw, zw);                     // L2 low
    highpass_kernel<2, true ><<<512, 512>>>(inputs, yw, zw, out);  // L2 high + <Z>
}

// round 12
// speedup vs baseline: 3.3095x; 3.3095x over previous
#include <cuda_runtime.h>
#include <math.h>

#define NA 8
#define R  16          // amps per thread
#define T  256         // threads (single block)
// 12 active qubits (global wires {0..9,17,18} -> local 0..9,10,11), 4096 amps.

__device__ __forceinline__ float2 cmul(float2 a, float2 b) {
    return make_float2(a.x * b.x - a.y * b.y, a.x * b.y + a.y * b.x);
}

// Fused single-qubit rotation (RZ?)*RY*RX for global wire gw of layer `layer`.
__device__ __forceinline__ void make_rot(int gw, int layer, bool withRZ,
                                         const float* __restrict__ inputs,
                                         const float* __restrict__ yw,
                                         const float* __restrict__ zw,
                                         float2 u[4])
{
    const float TWO_PI = 6.28318530717958647692f;
    const float PI_F   = 3.14159265358979323846f;
    float x = inputs[gw];
    float a;
    if (gw >= 17) {                            // directional wires 17,18
        a = (x >= 0.5f) ? PI_F : 0.0f;
    } else {                                   // [-1.5,1.5] -> [0,2pi], clip
        a = (x + 1.5f) * (TWO_PI / 3.0f);
        a = fminf(fmaxf(a, 0.0f), TWO_PI);
    }
    float sx, cx; sincosf(0.5f * a, &sx, &cx);
    float y = yw[layer * 19 + gw];
    float sy, cy; sincosf(0.5f * y, &sy, &cy);
    // M = RY*RX
    float2 m00 = make_float2(cy * cx,  sy * sx);
    float2 m01 = make_float2(-sy * cx, -cy * sx);
    float2 m10 = make_float2(sy * cx,  -cy * sx);
    float2 m11 = make_float2(cy * cx,  -sy * sx);
    if (withRZ) {
        float z = zw[layer * 19 + gw];
        float sz, cz; sincosf(0.5f * z, &sz, &cz);
        float2 e0 = make_float2(cz, -sz), e1 = make_float2(cz, sz);
        m00 = cmul(e0, m00); m01 = cmul(e0, m01);
        m10 = cmul(e1, m10); m11 = cmul(e1, m11);
    }
    u[0] = m00; u[1] = m01; u[2] = m10; u[3] = m11;
}

// Gate on register bit MB of the 16-amp register file.
template<int MB>
__device__ __forceinline__ void gate_reg(float* vr, float* vi, const float2* u)
{
    float2 u00 = u[0], u01 = u[1], u10 = u[2], u11 = u[3];
    #pragma unroll
    for (int r0 = 0; r0 < R; r0++) {
        if (r0 & MB) continue;
        int r1 = r0 | MB;
        float ar = vr[r0], ai = vi[r0], br = vr[r1], bi = vi[r1];
        vr[r0] = u00.x * ar - u00.y * ai + u01.x * br - u01.y * bi;
        vi[r0] = u00.x * ai + u00.y * ar + u01.x * bi + u01.y * br;
        vr[r1] = u10.x * ar - u10.y * ai + u11.x * br - u11.y * bi;
        vi[r1] = u10.x * ai + u10.y * ar + u11.x * bi + u11.y * br;
    }
}

// Gate on a lane bit (mask M) via warp shuffles.
template<int M>
__device__ __forceinline__ void gate_lane(float* vr, float* vi,
                                          unsigned lane, const float2* u)
{
    bool hi = (lane & M) != 0;
    float2 A = hi ? u[3] : u[0];
    float2 B = hi ? u[2] : u[1];
    #pragma unroll
    for (int r = 0; r < R; r++) {
        float wr = __shfl_xor_sync(0xFFFFFFFFu, vr[r], M);
        float wi = __shfl_xor_sync(0xFFFFFFFFu, vi[r], M);
        float ar = vr[r], ai = vi[r];
        vr[r] = A.x * ar - A.y * ai + B.x * wr - B.y * wi;
        vi[r] = A.x * ai + A.y * ar + B.x * wi + B.y * wr;
    }
}

// Phase-1 amp index: a0..4=t0..4 (w0-4), a5=t5,a6=t6 (w5,6), a7=r0 (w7),
// a8=r1 (w8), a9=t7 (w9), a10=r2 (w10), a11=r3 (w11).
__device__ __forceinline__ unsigned p1a(unsigned t, unsigned r)
{
    return (t & 0x7Fu) | ((r & 1u) << 7) | ((r & 2u) << 7)
         | ((t & 0x80u) << 2) | ((r & 4u) << 8) | ((r & 8u) << 8);
}
// Phase-2 amp index: a0..4=t0..4 (w0-4), a5..8=r0..3 (w5,6,7,8),
// a9=t5,a10=t6,a11=t7 (w9,10,11).
__device__ __forceinline__ unsigned p2a(unsigned t, unsigned r)
{
    return (t & 0x1Fu) | (r << 5) | ((t & 0xE0u) << 4);
}

// CZ0 kept pairs (local): (0,1)..(8,9), (10,11), (0,11).
__device__ __forceinline__ float cz0_sign(unsigned a)
{
    unsigned par = __popc((a & (a >> 1)) & 0x1FFu)
                 + ((a >> 10) & (a >> 11) & 1u)
                 + (a & (a >> 11) & 1u);
    return (par & 1u) ? -1.0f : 1.0f;
}
// CZ1 kept pairs (local): (0,1)..(7,8), (0,11).
__device__ __forceinline__ float cz1_sign(unsigned a)
{
    unsigned par = __popc((a & (a >> 1)) & 0xFFu) + (a & (a >> 11) & 1u);
    return (par & 1u) ? -1.0f : 1.0f;
}

__global__ void __launch_bounds__(T) qve_kernel(const float* __restrict__ inputs,
                                                const float* __restrict__ yw,
                                                const float* __restrict__ zw,
                                                float* __restrict__ out)
{
    __shared__ float2 sPhi[12][2];   // L0 columns per local wire
    __shared__ float2 sU1[12][4];    // L1 unitaries (used: 0..8, 11)
    __shared__ float2 sU2[8][4];     // L2 unitaries (wires 0..7)
    __shared__ float2 sF[16];        // init product over reg-bit wires {7,8,10,11}
    __shared__ float  sre[4096];
    __shared__ float  sim[4096];
    __shared__ float  sred[8][8];

    const unsigned tid  = threadIdx.x;
    const unsigned lane = tid & 31u;

    // ---- setup: build all needed unitaries (disjoint warps) ----
    if (tid < 12) {
        int v  = tid;
        int gw = v < 10 ? v : (v == 10 ? 17 : 18);
        bool withRZ = (v <= 8 || v == 11);     // RZ dropped on local 9,10 (g9,g17)
        float2 u[4];
        make_rot(gw, 0, withRZ, inputs, yw, zw, u);
        sPhi[v][0] = u[0];                     // column 0 of U0
        sPhi[v][1] = u[2];
    } else if (tid >= 32 && tid < 44) {
        int v = tid - 32;
        if (v <= 8 || v == 11) {
            int gw = (v == 11) ? 18 : v;
            bool withRZ = (v <= 7);            // RZ dropped on 8 and 18
            float2 u[4];
            make_rot(gw, 1, withRZ, inputs, yw, zw, u);
            sU1[v][0] = u[0]; sU1[v][1] = u[1]; sU1[v][2] = u[2]; sU1[v][3] = u[3];
        }
    } else if (tid >= 64 && tid < 72) {
        int v = tid - 64;
        float2 u[4];
        make_rot(v, 2, false, inputs, yw, zw, u);   // L2: RY*RX only
        sU2[v][0] = u[0]; sU2[v][1] = u[1]; sU2[v][2] = u[2]; sU2[v][3] = u[3];
    }
    __syncthreads();
    if (tid < 16) {
        float2 f = sPhi[7][tid & 1u];
        f = cmul(f, sPhi[8][(tid >> 1) & 1u]);
        f = cmul(f, sPhi[10][(tid >> 2) & 1u]);
        f = cmul(f, sPhi[11][(tid >> 3) & 1u]);
        sF[tid] = f;
    }
    __syncthreads();

    // ---- init: L0 product state + CZ0 sign, phase-1 layout ----
    float2 C = sPhi[0][tid & 1u];
    C = cmul(C, sPhi[1][(tid >> 1) & 1u]);
    C = cmul(C, sPhi[2][(tid >> 2) & 1u]);
    C = cmul(C, sPhi[3][(tid >> 3) & 1u]);
    C = cmul(C, sPhi[4][(tid >> 4) & 1u]);
    C = cmul(C, sPhi[5][(tid >> 5) & 1u]);
    C = cmul(C, sPhi[6][(tid >> 6) & 1u]);
    C = cmul(C, sPhi[9][(tid >> 7) & 1u]);

    float vr[R], vi[R];
    #pragma unroll
    for (int r = 0; r < R; r++) {
        unsigned a = p1a(tid, (unsigned)r);
        float2 amp = cmul(C, sF[r]);
        float s = cz0_sign(a);
        vr[r] = s * amp.x; vi[r] = s * amp.y;
    }

    // ---- phase 1: L1 on wires 0-4 (lane), 7,8,11 (reg) ----
    gate_lane<1 >(vr, vi, lane, sU1[0]);
    gate_lane<2 >(vr, vi, lane, sU1[1]);
    gate_lane<4 >(vr, vi, lane, sU1[2]);
    gate_lane<8 >(vr, vi, lane, sU1[3]);
    gate_lane<16>(vr, vi, lane, sU1[4]);
    gate_reg<1>(vr, vi, sU1[7]);     // wire 7  = r bit0
    gate_reg<2>(vr, vi, sU1[8]);     // wire 8  = r bit1
    gate_reg<8>(vr, vi, sU1[11]);    // wire 11 = r bit3

    // ---- transpose to phase-2 layout (conflict-free: lane bits stay a[4:0]) ----
    #pragma unroll
    for (int r = 0; r < R; r++) {
        unsigned a = p1a(tid, (unsigned)r);
        sre[a] = vr[r]; sim[a] = vi[r];
    }
    __syncthreads();
    #pragma unroll
    for (int r = 0; r < R; r++) {
        unsigned a = p2a(tid, (unsigned)r);
        vr[r] = sre[a]; vi[r] = sim[a];
    }

    // ---- phase 2: finish L1 (wires 5,6), CZ1 sign, full L2 (wires 0-7) ----
    gate_reg<1>(vr, vi, sU1[5]);     // wire 5 = r bit0
    gate_reg<2>(vr, vi, sU1[6]);     // wire 6 = r bit1

    #pragma unroll
    for (int r = 0; r < R; r++) {
        float s = cz1_sign(p2a(tid, (unsigned)r));
        vr[r] *= s; vi[r] *= s;
    }

    gate_lane<1 >(vr, vi, lane, sU2[0]);
    gate_lane<2 >(vr, vi, lane, sU2[1]);
    gate_lane<4 >(vr, vi, lane, sU2[2]);
    gate_lane<8 >(vr, vi, lane, sU2[3]);
    gate_lane<16>(vr, vi, lane, sU2[4]);
    gate_reg<1>(vr, vi, sU2[5]);     // wire 5
    gate_reg<2>(vr, vi, sU2[6]);     // wire 6
    gate_reg<4>(vr, vi, sU2[7]);     // wire 7

    // ---- <Z_w> reduction, w = 0..7 ----
    // wires 0-4 = lane bits t[4:0] (uniform per thread); 5,6,7 = r bits 0,1,2.
    float P = 0.f, S5 = 0.f, S6 = 0.f, S7 = 0.f;
    #pragma unroll
    for (int r = 0; r < R; r++) {
        float p = vr[r] * vr[r] + vi[r] * vi[r];
        P  += p;
        S5 += (r & 1) ? -p : p;
        S6 += (r & 2) ? -p : p;
        S7 += (r & 4) ? -p : p;
    }
    float z[8];
    #pragma unroll
    for (int v = 0; v < 5; v++) z[v] = ((tid >> v) & 1u) ? -P : P;
    z[5] = S5; z[6] = S6; z[7] = S7;
    #pragma unroll
    for (int v = 0; v < 8; v++) {
        #pragma unroll
        for (int o = 16; o > 0; o >>= 1)
            z[v] += __shfl_xor_sync(0xFFFFFFFFu, z[v], o);
    }
    if (lane == 0) {
        unsigned wi = tid >> 5;              // 8 warps
        #pragma unroll
        for (int v = 0; v < 8; v++) sred[wi][v] = z[v];
    }
    __syncthreads();
    if (tid < 8) {
        float s = 0.f;
        #pragma unroll
        for (int w = 0; w < 8; w++) s += sred[w][tid];
        out[tid] = s;
    }
}

extern "C" void kernel_launch(void* const* d_in, const int* in_sizes, int n_in,
                              void* d_out, int out_size)
{
    (void)in_sizes; (void)n_in; (void)out_size;
    const float* inputs = (const float*)d_in[0];
    const float* yw     = (const float*)d_in[1];
    const float* zw     = (const float*)d_in[2];
    float* out = (float*)d_out;

    qve_kernel<<<1, T>>>(inputs, yw, zw, out);
}